// round 7
// baseline (speedup 1.0000x reference)
#include <cuda_runtime.h>

// Per-quaternion L2 normalize: (65536, 1024) fp32 = 2^24 quats. 512 MiB stream.
// R1 MLP 32B/thr:  5955 GB/s
// R2 MLP 64B T256: 6479 GB/s  kernel 74.3us  <- plateau
// R3 MLP 128B:     6324 GB/s  (regs 40 -> occ 62%) regression
// R4 MLP 64B T512: 6451 GB/s  plateau
// R5 persistent:   6077 GB/s  regression (loop deps)
// R6 2x256b:       6491 GB/s  kernel 74.2us  plateau
// R7: 3x256-bit loads/thread = 96B in flight @ ~36 regs (7 CTAs/SM).
//     Probes the untested cell of (in-flight bytes x occupancy).

struct f8 { float v[8]; };

static __device__ __forceinline__ f8 ldg256_cs(const float* p) {
    f8 r;
    asm volatile("ld.global.cs.v8.f32 {%0,%1,%2,%3,%4,%5,%6,%7}, [%8];"
                 : "=f"(r.v[0]), "=f"(r.v[1]), "=f"(r.v[2]), "=f"(r.v[3]),
                   "=f"(r.v[4]), "=f"(r.v[5]), "=f"(r.v[6]), "=f"(r.v[7])
                 : "l"(p));
    return r;
}

static __device__ __forceinline__ void stg256_cs(float* p, const f8& r) {
    asm volatile("st.global.cs.v8.f32 [%0], {%1,%2,%3,%4,%5,%6,%7,%8};"
                 :: "l"(p),
                    "f"(r.v[0]), "f"(r.v[1]), "f"(r.v[2]), "f"(r.v[3]),
                    "f"(r.v[4]), "f"(r.v[5]), "f"(r.v[6]), "f"(r.v[7])
                 : "memory");
}

static __device__ __forceinline__ void norm2(f8& q) {
    float s0 = q.v[0]*q.v[0] + q.v[1]*q.v[1] + q.v[2]*q.v[2] + q.v[3]*q.v[3];
    float s1 = q.v[4]*q.v[4] + q.v[5]*q.v[5] + q.v[6]*q.v[6] + q.v[7]*q.v[7];
    float i0 = (s0 == 0.0f) ? 1.0f : rsqrtf(s0);
    float i1 = (s1 == 0.0f) ? 1.0f : rsqrtf(s1);
    q.v[0] *= i0; q.v[1] *= i0; q.v[2] *= i0; q.v[3] *= i0;
    q.v[4] *= i1; q.v[5] *= i1; q.v[6] *= i1; q.v[7] *= i1;
}

__global__ void __launch_bounds__(256)
quat_normalize_v8x3(const float* __restrict__ in, float* __restrict__ out) {
    const int T = 256;
    // Each thread: 3 x 256-bit loads (6 quats). Block covers 1536 quats.
    long long q0 = (long long)blockIdx.x * (T * 6) + threadIdx.x * 2;

    const float* p0 = in + q0 * 4;
    f8 a = ldg256_cs(p0);
    f8 b = ldg256_cs(p0 + (T * 2) * 4);
    f8 c = ldg256_cs(p0 + (T * 4) * 4);

    float* o0 = out + q0 * 4;
    norm2(a);
    stg256_cs(o0, a);
    norm2(b);
    stg256_cs(o0 + (T * 2) * 4, b);
    norm2(c);
    stg256_cs(o0 + (T * 4) * 4, c);
}

static __device__ __forceinline__ float4 norm_quat(float4 v) {
    float s = v.x * v.x + v.y * v.y + v.z * v.z + v.w * v.w;
    float inv = (s == 0.0f) ? 1.0f : rsqrtf(s);
    v.x *= inv; v.y *= inv; v.z *= inv; v.w *= inv;
    return v;
}

__global__ void __launch_bounds__(256)
quat_normalize_tail_kernel(const float4* __restrict__ in,
                           float4* __restrict__ out,
                           int n_quat) {
    int i = blockIdx.x * blockDim.x + threadIdx.x;
    if (i < n_quat) out[i] = norm_quat(__ldcs(&in[i]));
}

extern "C" void kernel_launch(void* const* d_in, const int* in_sizes, int n_in,
                              void* d_out, int out_size) {
    const float* x = (const float*)d_in[0];
    float* y = (float*)d_out;
    int n_quat = in_sizes[0] / 4;   // 16,777,216

    const int threads = 256;
    const int quats_per_block = threads * 6;  // 1536

    int main_blocks = n_quat / quats_per_block;      // 10922
    if (main_blocks > 0)
        quat_normalize_v8x3<<<main_blocks, threads>>>(x, y);

    int done = main_blocks * quats_per_block;
    int rem = n_quat - done;                          // 904
    if (rem > 0)
        quat_normalize_tail_kernel<<<(rem + 255) / 256, 256>>>(
            (const float4*)(x + (long long)done * 4),
            (float4*)(y + (long long)done * 4), rem);
}

// round 8
// speedup vs baseline: 1.0262x; 1.0262x over previous
#include <cuda_runtime.h>

// Per-quaternion L2 normalize: (65536, 1024) fp32 = 2^24 quats.
// 512 MiB mandatory HBM traffic (256 in + 256 out).
//
// Optimization history (GB300, sm_103a):
//   R1 MLP2  T256:        5955 GB/s   wall 82.7us
//   R2 MLP4  T256:        6479 GB/s   wall 82.0us   <- plateau
//   R3 MLP8  T256:        6324 GB/s   (regs 40 -> occ 62%) regression
//   R4 MLP4  T512:        6451 GB/s   wall 81.95us  <- BEST wall
//   R5 persistent loop:   6077 GB/s   wall 92.2us   regression
//   R6 2x256-bit ld/st:   6491 GB/s   wall 82.3us   == plateau
//   R7 3x256-bit + tail:  plateau + launch overhead, wall 84.1us
//
// Conclusion: four structurally different instruction mixes saturate at
// ~6.49 TB/s. 512 MiB / 6.49 TB/s = 82.7us == the pinned wall. This is the
// HBM3e read+write streaming ceiling on this part (~81% of 8 TB/s spec);
// traffic is irreducible. Final kernel = best measured config (R4).

static __device__ __forceinline__ float4 norm_quat(float4 v) {
    float s = v.x * v.x + v.y * v.y + v.z * v.z + v.w * v.w;
    // reference semantics: ||x||==0 -> divide by 1 (pass through).
    float inv = (s == 0.0f) ? 1.0f : rsqrtf(s);
    v.x *= inv; v.y *= inv; v.z *= inv; v.w *= inv;
    return v;
}

__global__ void __launch_bounds__(512)
quat_normalize_kernel(const float4* __restrict__ in,
                      float4* __restrict__ out) {
    const int T = 512;
    int base = blockIdx.x * (T * 4) + threadIdx.x;

    // Front-batch 4 independent, warp-coalesced 16B loads (MLP_p1 = 4,
    // 64B in flight per thread — the measured optimum), streaming hints.
    float4 a = __ldcs(&in[base]);
    float4 b = __ldcs(&in[base + T]);
    float4 c = __ldcs(&in[base + 2 * T]);
    float4 d = __ldcs(&in[base + 3 * T]);

    // Store each result as soon as it's ready: short live ranges (30 regs),
    // early start of the write stream.
    a = norm_quat(a);
    __stcs(&out[base], a);
    b = norm_quat(b);
    __stcs(&out[base + T], b);
    c = norm_quat(c);
    __stcs(&out[base + 2 * T], c);
    d = norm_quat(d);
    __stcs(&out[base + 3 * T], d);
}

// Bounds-checked fallback for non-multiple sizes (unused for 2^24 quats).
__global__ void __launch_bounds__(256)
quat_normalize_tail_kernel(const float4* __restrict__ in,
                           float4* __restrict__ out,
                           int n_quat) {
    int i = blockIdx.x * blockDim.x + threadIdx.x;
    if (i < n_quat) out[i] = norm_quat(__ldcs(&in[i]));
}

extern "C" void kernel_launch(void* const* d_in, const int* in_sizes, int n_in,
                              void* d_out, int out_size) {
    const float4* x = (const float4*)d_in[0];
    float4* y = (float4*)d_out;
    int n_quat = in_sizes[0] / 4;   // 16,777,216

    const int threads = 512;
    const int per_block = threads * 4;  // 2048 quats/block

    if (n_quat % per_block == 0) {
        quat_normalize_kernel<<<n_quat / per_block, threads>>>(x, y);  // 8192 blocks
    } else {
        int main_blocks = n_quat / per_block;
        if (main_blocks > 0)
            quat_normalize_kernel<<<main_blocks, threads>>>(x, y);
        int done = main_blocks * per_block;
        int rem = n_quat - done;
        if (rem > 0)
            quat_normalize_tail_kernel<<<(rem + 255) / 256, 256>>>(
                x + done, y + done, rem);
    }
}